// round 2
// baseline (speedup 1.0000x reference)
#include <cuda_runtime.h>
#include <math.h>

#define IN_CH   512
#define NHEADS  8
#define C1DIM   8
#define H1DIM   64      // NHEADS*C1DIM
#define OUT_CH  128
#define NMAX    50000
#define EMAX    800000

// ------------------ scratch (static device globals; no allocs) ---------------
__device__ float g_h1   [NMAX * H1DIM];    // conv1 linear output
__device__ float g_s1   [NMAX * NHEADS];
__device__ float g_d1   [NMAX * NHEADS];
__device__ float g_denom1[NMAX * NHEADS];
__device__ float g_agg1 [NMAX * H1DIM];
__device__ float g_h1b  [NMAX * H1DIM];    // elu(conv1) -> input of conv2
__device__ float g_h2   [NMAX * OUT_CH];   // conv2 linear output
__device__ float g_s2   [NMAX];
__device__ float g_d2   [NMAX];
__device__ float g_denom2[NMAX];
__device__ float g_agg2 [NMAX * OUT_CH];

// ------------------ SGEMM: C[M,N] = A[M,K] @ B[K,N]  (BM=128,BN=64,BK=32) ----
__global__ void __launch_bounds__(256)
sgemm128x64(const float* __restrict__ A, const float* __restrict__ B,
            float* __restrict__ C, int M, int N, int K)
{
    const int BM = 128, BN = 64, BK = 32;
    __shared__ float As[BK][BM + 4];
    __shared__ float Bs[BK][BN];

    int tid = threadIdx.x;
    int tx  = tid & 15;    // col group (4 cols)
    int ty  = tid >> 4;    // row group (8 rows)
    int m0  = blockIdx.x * BM;
    int n0  = blockIdx.y * BN;

    float acc[8][4];
#pragma unroll
    for (int i = 0; i < 8; i++)
#pragma unroll
        for (int j = 0; j < 4; j++) acc[i][j] = 0.f;

    for (int k0 = 0; k0 < K; k0 += BK) {
        // A tile: 128 rows x 32 k  (1024 float4 loads, 4 per thread)
#pragma unroll
        for (int i = 0; i < 4; i++) {
            int id = tid + 256 * i;
            int r  = id >> 3;       // 0..127
            int kq = id & 7;        // 0..7  (k quad)
            float4 v = make_float4(0.f, 0.f, 0.f, 0.f);
            int gr = m0 + r;
            if (gr < M)
                v = *(const float4*)(A + (size_t)gr * K + k0 + kq * 4);
            As[kq * 4 + 0][r] = v.x;
            As[kq * 4 + 1][r] = v.y;
            As[kq * 4 + 2][r] = v.z;
            As[kq * 4 + 3][r] = v.w;
        }
        // B tile: 32 k x 64 n (512 float4 loads, 2 per thread)
#pragma unroll
        for (int i = 0; i < 2; i++) {
            int id = tid + 256 * i;
            int kk = id >> 4;       // 0..31
            int nq = id & 15;       // 0..15
            float4 v = *(const float4*)(B + (size_t)(k0 + kk) * N + n0 + nq * 4);
            *(float4*)&Bs[kk][nq * 4] = v;
        }
        __syncthreads();

#pragma unroll
        for (int kk = 0; kk < BK; kk++) {
            float4 a0 = *(const float4*)&As[kk][ty * 8];
            float4 a1 = *(const float4*)&As[kk][ty * 8 + 4];
            float4 bv = *(const float4*)&Bs[kk][tx * 4];
            float a[8] = {a0.x, a0.y, a0.z, a0.w, a1.x, a1.y, a1.z, a1.w};
            float b[4] = {bv.x, bv.y, bv.z, bv.w};
#pragma unroll
            for (int i = 0; i < 8; i++)
#pragma unroll
                for (int j = 0; j < 4; j++)
                    acc[i][j] = fmaf(a[i], b[j], acc[i][j]);
        }
        __syncthreads();
    }

#pragma unroll
    for (int i = 0; i < 8; i++) {
        int gr = m0 + ty * 8 + i;
        if (gr < M) {
            float4 v = make_float4(acc[i][0], acc[i][1], acc[i][2], acc[i][3]);
            *(float4*)(C + (size_t)gr * N + n0 + tx * 4) = v;
        }
    }
}

// ------------------ layer-1 per-node attention coefficients ------------------
__global__ void sd1_kernel(const float* __restrict__ att_src,
                           const float* __restrict__ att_dst, int n)
{
    int i = blockIdx.x * blockDim.x + threadIdx.x;
    if (i >= n * NHEADS) return;
    int node = i >> 3, h = i & 7;
    const float* hp = g_h1 + node * H1DIM + h * C1DIM;
    float s = 0.f, d = 0.f;
#pragma unroll
    for (int c = 0; c < 8; c++) {
        float v = hp[c];
        s = fmaf(v, att_src[h * 8 + c], s);
        d = fmaf(v, att_dst[h * 8 + c], d);
    }
    g_s1[i] = s;
    g_d1[i] = d;
}

// ------------------ layer-1 fused edge pass (exp + denom + aggregate) --------
// thread = (edge, 4-channel group); 16 groups cover the 64 channels
__global__ void edge1_kernel(const int* __restrict__ src,
                             const int* __restrict__ dst, int ne, int n)
{
    int idx = blockIdx.x * blockDim.x + threadIdx.x;
    int items = (ne + n) * 16;
    if (idx >= items) return;
    int e  = idx >> 4;
    int c4 = idx & 15;
    int sN, dN;
    if (e < ne) { sN = src[e]; dN = dst[e]; }
    else        { sN = dN = e - ne; }
    int h = c4 >> 1;
    float a = g_s1[sN * NHEADS + h] + g_d1[dN * NHEADS + h];
    a = (a > 0.f) ? a : 0.2f * a;           // leaky relu
    float ea = __expf(a);                   // global shift cancels in softmax
    if ((c4 & 1) == 0) atomicAdd(&g_denom1[dN * NHEADS + h], ea);
    float4 hv = *(const float4*)(g_h1 + sN * H1DIM + c4 * 4);
    float* ap = g_agg1 + dN * H1DIM + c4 * 4;
    atomicAdd(ap + 0, ea * hv.x);
    atomicAdd(ap + 1, ea * hv.y);
    atomicAdd(ap + 2, ea * hv.z);
    atomicAdd(ap + 3, ea * hv.w);
}

// ------------------ layer-1 finalize: normalize + bias + elu -----------------
__global__ void fin1_kernel(const float* __restrict__ bias, int n)
{
    int i = blockIdx.x * blockDim.x + threadIdx.x;
    if (i >= n * H1DIM) return;
    int node = i >> 6, c = i & 63, h = c >> 3;
    float v = g_agg1[i] / g_denom1[node * NHEADS + h] + bias[c];
    g_h1b[i] = (v > 0.f) ? v : expm1f(v);
}

// ------------------ layer-2 per-node attention coefficients (warp/node) ------
__global__ void sd2_kernel(const float* __restrict__ att_src,
                           const float* __restrict__ att_dst, int n)
{
    int gt   = blockIdx.x * blockDim.x + threadIdx.x;
    int node = gt >> 5;
    int lane = gt & 31;
    if (node >= n) return;
    float4 hv = *(const float4*)(g_h2 + (size_t)node * OUT_CH + lane * 4);
    float4 as = *(const float4*)(att_src + lane * 4);
    float4 ad = *(const float4*)(att_dst + lane * 4);
    float s = hv.x * as.x + hv.y * as.y + hv.z * as.z + hv.w * as.w;
    float d = hv.x * ad.x + hv.y * ad.y + hv.z * ad.z + hv.w * ad.w;
#pragma unroll
    for (int off = 16; off > 0; off >>= 1) {
        s += __shfl_down_sync(0xffffffffu, s, off);
        d += __shfl_down_sync(0xffffffffu, d, off);
    }
    if (lane == 0) { g_s2[node] = s; g_d2[node] = d; }
}

// ------------------ layer-2 fused edge pass ----------------------------------
__global__ void edge2_kernel(const int* __restrict__ src,
                             const int* __restrict__ dst, int ne, int n)
{
    int idx = blockIdx.x * blockDim.x + threadIdx.x;
    int items = (ne + n) * 32;
    if (idx >= items) return;
    int e  = idx >> 5;
    int c4 = idx & 31;
    int sN, dN;
    if (e < ne) { sN = src[e]; dN = dst[e]; }
    else        { sN = dN = e - ne; }
    float a = g_s2[sN] + g_d2[dN];
    a = (a > 0.f) ? a : 0.2f * a;
    float ea = __expf(a);
    if (c4 == 0) atomicAdd(&g_denom2[dN], ea);
    float4 hv = *(const float4*)(g_h2 + (size_t)sN * OUT_CH + c4 * 4);
    float* ap = g_agg2 + (size_t)dN * OUT_CH + c4 * 4;
    atomicAdd(ap + 0, ea * hv.x);
    atomicAdd(ap + 1, ea * hv.y);
    atomicAdd(ap + 2, ea * hv.z);
    atomicAdd(ap + 3, ea * hv.w);
}

// ------------------ layer-2 finalize into d_out ------------------------------
__global__ void fin2_kernel(const float* __restrict__ bias,
                            float* __restrict__ out, int n)
{
    int i = blockIdx.x * blockDim.x + threadIdx.x;
    if (i >= n * OUT_CH) return;
    int node = i >> 7, c = i & 127;
    float v = g_agg2[i] / g_denom2[node] + bias[c];
    out[i] = (v > 0.f) ? v : expm1f(v);
}

// ------------------ launch ---------------------------------------------------
extern "C" void kernel_launch(void* const* d_in, const int* in_sizes, int n_in,
                              void* d_out, int out_size)
{
    const float* x   = (const float*)d_in[0];
    const int*   ei  = (const int*)  d_in[1];
    const float* W1  = (const float*)d_in[2];
    const float* as1 = (const float*)d_in[3];
    const float* ad1 = (const float*)d_in[4];
    const float* b1  = (const float*)d_in[5];
    const float* W2  = (const float*)d_in[6];
    const float* as2 = (const float*)d_in[7];
    const float* ad2 = (const float*)d_in[8];
    const float* b2  = (const float*)d_in[9];
    float* out = (float*)d_out;

    int n = in_sizes[0] / IN_CH;
    int e = in_sizes[1] / 2;
    const int* src = ei;
    const int* dst = ei + e;

    void *p_h1, *p_h1b, *p_h2, *p;
    cudaGetSymbolAddress(&p_h1,  g_h1);
    cudaGetSymbolAddress(&p_h1b, g_h1b);
    cudaGetSymbolAddress(&p_h2,  g_h2);

    // zero accumulators
    cudaGetSymbolAddress(&p, g_denom1); cudaMemsetAsync(p, 0, (size_t)n * NHEADS * 4);
    cudaGetSymbolAddress(&p, g_agg1);   cudaMemsetAsync(p, 0, (size_t)n * H1DIM  * 4);
    cudaGetSymbolAddress(&p, g_denom2); cudaMemsetAsync(p, 0, (size_t)n * 4);
    cudaGetSymbolAddress(&p, g_agg2);   cudaMemsetAsync(p, 0, (size_t)n * OUT_CH * 4);

    // ---- layer 1 ----
    {
        dim3 grid((n + 127) / 128, H1DIM / 64);
        sgemm128x64<<<grid, 256>>>(x, W1, (float*)p_h1, n, H1DIM, IN_CH);
    }
    sd1_kernel<<<(n * NHEADS + 255) / 256, 256>>>(as1, ad1, n);
    {
        int items = (e + n) * 16;
        edge1_kernel<<<(items + 255) / 256, 256>>>(src, dst, e, n);
    }
    fin1_kernel<<<(n * H1DIM + 255) / 256, 256>>>(b1, n);

    // ---- layer 2 ----
    {
        dim3 grid((n + 127) / 128, OUT_CH / 64);
        sgemm128x64<<<grid, 256>>>((const float*)p_h1b, W2, (float*)p_h2, n, OUT_CH, H1DIM);
    }
    sd2_kernel<<<(n * 32 + 255) / 256, 256>>>(as2, ad2, n);
    {
        int items = (e + n) * 32;
        edge2_kernel<<<(items + 255) / 256, 256>>>(src, dst, e, n);
    }
    fin2_kernel<<<(n * OUT_CH + 255) / 256, 256>>>(b2, out, n);
}

// round 3
// speedup vs baseline: 1.9448x; 1.9448x over previous
#include <cuda_runtime.h>
#include <math.h>

#define IN_CH   512
#define NHEADS  8
#define H1DIM   64
#define OUT_CH  128
#define NMAX    50000
#define EMAX    800000
#define ETOT    (EMAX + NMAX)

// ------------------ scratch (static device globals; no allocs) ---------------
__device__ float g_h1   [NMAX * H1DIM];    // conv1 linear output
__device__ float g_s1   [NMAX * NHEADS];
__device__ float g_d1   [NMAX * NHEADS];
__device__ float g_h1b  [NMAX * H1DIM];    // elu(conv1) -> input of conv2
__device__ float g_h2   [NMAX * OUT_CH];   // conv2 linear output
__device__ float g_s2   [NMAX];
__device__ float g_d2   [NMAX];
// CSR (built per launch; includes self-loops)
__device__ int   g_deg   [NMAX];
__device__ int   g_rowptr[NMAX + 1];
__device__ int   g_cur   [NMAX];
__device__ int   g_csrc  [ETOT];

// ------------------ SGEMM: C[M,N] = A[M,K] @ B[K,N]  (BM=128,BN=64,BK=32) ----
__global__ void __launch_bounds__(256)
sgemm128x64(const float* __restrict__ A, const float* __restrict__ B,
            float* __restrict__ C, int M, int N, int K)
{
    const int BM = 128, BN = 64, BK = 32;
    __shared__ float As[BK][BM + 4];
    __shared__ float Bs[BK][BN];

    int tid = threadIdx.x;
    int tx  = tid & 15;
    int ty  = tid >> 4;
    int m0  = blockIdx.x * BM;
    int n0  = blockIdx.y * BN;

    float acc[8][4];
#pragma unroll
    for (int i = 0; i < 8; i++)
#pragma unroll
        for (int j = 0; j < 4; j++) acc[i][j] = 0.f;

    for (int k0 = 0; k0 < K; k0 += BK) {
#pragma unroll
        for (int i = 0; i < 4; i++) {
            int id = tid + 256 * i;
            int r  = id >> 3;
            int kq = id & 7;
            float4 v = make_float4(0.f, 0.f, 0.f, 0.f);
            int gr = m0 + r;
            if (gr < M)
                v = *(const float4*)(A + (size_t)gr * K + k0 + kq * 4);
            As[kq * 4 + 0][r] = v.x;
            As[kq * 4 + 1][r] = v.y;
            As[kq * 4 + 2][r] = v.z;
            As[kq * 4 + 3][r] = v.w;
        }
#pragma unroll
        for (int i = 0; i < 2; i++) {
            int id = tid + 256 * i;
            int kk = id >> 4;
            int nq = id & 15;
            float4 v = *(const float4*)(B + (size_t)(k0 + kk) * N + n0 + nq * 4);
            *(float4*)&Bs[kk][nq * 4] = v;
        }
        __syncthreads();

#pragma unroll
        for (int kk = 0; kk < BK; kk++) {
            float4 a0 = *(const float4*)&As[kk][ty * 8];
            float4 a1 = *(const float4*)&As[kk][ty * 8 + 4];
            float4 bv = *(const float4*)&Bs[kk][tx * 4];
            float a[8] = {a0.x, a0.y, a0.z, a0.w, a1.x, a1.y, a1.z, a1.w};
            float b[4] = {bv.x, bv.y, bv.z, bv.w};
#pragma unroll
            for (int i = 0; i < 8; i++)
#pragma unroll
                for (int j = 0; j < 4; j++)
                    acc[i][j] = fmaf(a[i], b[j], acc[i][j]);
        }
        __syncthreads();
    }

#pragma unroll
    for (int i = 0; i < 8; i++) {
        int gr = m0 + ty * 8 + i;
        if (gr < M) {
            float4 v = make_float4(acc[i][0], acc[i][1], acc[i][2], acc[i][3]);
            *(float4*)(C + (size_t)gr * N + n0 + tx * 4) = v;
        }
    }
}

// ------------------ CSR build ------------------------------------------------
__global__ void count_kernel(const int* __restrict__ dst, int ne, int n)
{
    int i = blockIdx.x * blockDim.x + threadIdx.x;
    if (i >= ne + n) return;
    int d = (i < ne) ? dst[i] : (i - ne);
    atomicAdd(&g_deg[d], 1);
}

// single-block exclusive scan, 4 elements/thread per tile (tile = 4096)
__global__ void __launch_bounds__(1024) scan_kernel(int n)
{
    __shared__ int warpsums[32];
    __shared__ int s_carry;
    int tid = threadIdx.x, lane = tid & 31, wid = tid >> 5;
    if (tid == 0) s_carry = 0;
    __syncthreads();

    for (int base = 0; base < n; base += 4096) {
        int i0 = base + tid * 4;
        int v[4];
#pragma unroll
        for (int k = 0; k < 4; k++) {
            int i = i0 + k;
            v[k] = (i < n) ? g_deg[i] : 0;
        }
        int tsum = v[0] + v[1] + v[2] + v[3];
        int x = tsum;
#pragma unroll
        for (int off = 1; off < 32; off <<= 1) {
            int t = __shfl_up_sync(0xffffffffu, x, off);
            if (lane >= off) x += t;
        }
        if (lane == 31) warpsums[wid] = x;
        __syncthreads();
        if (wid == 0) {
            int w = warpsums[lane];
#pragma unroll
            for (int off = 1; off < 32; off <<= 1) {
                int t = __shfl_up_sync(0xffffffffu, w, off);
                if (lane >= off) w += t;
            }
            warpsums[lane] = w;
        }
        __syncthreads();
        int warp_off = (wid > 0) ? warpsums[wid - 1] : 0;
        int run = s_carry + warp_off + (x - tsum);
#pragma unroll
        for (int k = 0; k < 4; k++) {
            int i = i0 + k;
            if (i < n) { g_rowptr[i] = run; g_cur[i] = run; }
            run += v[k];
        }
        __syncthreads();
        if (tid == 0) s_carry += warpsums[31];
        __syncthreads();
    }
    if (threadIdx.x == 0) g_rowptr[n] = s_carry;
}

__global__ void scatter_kernel(const int* __restrict__ src,
                               const int* __restrict__ dst, int ne, int n)
{
    int i = blockIdx.x * blockDim.x + threadIdx.x;
    if (i >= ne + n) return;
    int s, d;
    if (i < ne) { s = src[i]; d = dst[i]; }
    else        { s = d = i - ne; }
    int pos = atomicAdd(&g_cur[d], 1);
    g_csrc[pos] = s;
}

// ------------------ layer-1 per-node attention coefficients ------------------
__global__ void sd1_kernel(const float* __restrict__ att_src,
                           const float* __restrict__ att_dst, int n)
{
    int i = blockIdx.x * blockDim.x + threadIdx.x;
    if (i >= n * NHEADS) return;
    int node = i >> 3, h = i & 7;
    const float* hp = g_h1 + node * H1DIM + h * 8;
    float s = 0.f, d = 0.f;
#pragma unroll
    for (int c = 0; c < 8; c++) {
        float v = hp[c];
        s = fmaf(v, att_src[h * 8 + c], s);
        d = fmaf(v, att_dst[h * 8 + c], d);
    }
    g_s1[i] = s;
    g_d1[i] = d;
}

// ------------------ layer-1 gather (softmax + aggregate + bias + elu) --------
// one warp per destination node; lane covers 2 of 64 channels (head = lane/4)
__global__ void __launch_bounds__(256) gather1_kernel(const float* __restrict__ bias, int n)
{
    int gw   = (blockIdx.x * blockDim.x + threadIdx.x) >> 5;
    int lane = threadIdx.x & 31;
    if (gw >= n) return;
    int h = lane >> 2;
    float dv = g_d1[gw * NHEADS + h];
    int j0 = g_rowptr[gw], j1 = g_rowptr[gw + 1];
    float acc0 = 0.f, acc1 = 0.f, den = 0.f;
    int s = g_csrc[j0];                // deg >= 1 (self loop)
    for (int j = j0; j < j1; j++) {
        int snext = (j + 1 < j1) ? g_csrc[j + 1] : 0;
        float sv = g_s1[s * NHEADS + h];
        float a = sv + dv;
        a = (a > 0.f) ? a : 0.2f * a;
        float ea = __expf(a);          // global softmax shift cancels
        den += ea;
        float2 hv = *(const float2*)(g_h1 + s * H1DIM + lane * 2);
        acc0 = fmaf(ea, hv.x, acc0);
        acc1 = fmaf(ea, hv.y, acc1);
        s = snext;
    }
    float inv = 1.f / den;
    int c = lane * 2;
    float v0 = acc0 * inv + bias[c];
    float v1 = acc1 * inv + bias[c + 1];
    v0 = (v0 > 0.f) ? v0 : expm1f(v0);
    v1 = (v1 > 0.f) ? v1 : expm1f(v1);
    *(float2*)(g_h1b + gw * H1DIM + c) = make_float2(v0, v1);
}

// ------------------ layer-2 per-node attention coefficients ------------------
__global__ void sd2_kernel(const float* __restrict__ att_src,
                           const float* __restrict__ att_dst, int n)
{
    int gt   = blockIdx.x * blockDim.x + threadIdx.x;
    int node = gt >> 5;
    int lane = gt & 31;
    if (node >= n) return;
    float4 hv = *(const float4*)(g_h2 + (size_t)node * OUT_CH + lane * 4);
    float4 as = *(const float4*)(att_src + lane * 4);
    float4 ad = *(const float4*)(att_dst + lane * 4);
    float s = hv.x * as.x + hv.y * as.y + hv.z * as.z + hv.w * as.w;
    float d = hv.x * ad.x + hv.y * ad.y + hv.z * ad.z + hv.w * ad.w;
#pragma unroll
    for (int off = 16; off > 0; off >>= 1) {
        s += __shfl_down_sync(0xffffffffu, s, off);
        d += __shfl_down_sync(0xffffffffu, d, off);
    }
    if (lane == 0) { g_s2[node] = s; g_d2[node] = d; }
}

// ------------------ layer-2 gather -> final output ---------------------------
// one warp per node; lane covers 4 of 128 channels
__global__ void __launch_bounds__(256) gather2_kernel(const float* __restrict__ bias,
                                                      float* __restrict__ out, int n)
{
    int gw   = (blockIdx.x * blockDim.x + threadIdx.x) >> 5;
    int lane = threadIdx.x & 31;
    if (gw >= n) return;
    float dv = g_d2[gw];
    int j0 = g_rowptr[gw], j1 = g_rowptr[gw + 1];
    float a0 = 0.f, a1 = 0.f, a2 = 0.f, a3 = 0.f, den = 0.f;
    int s = g_csrc[j0];
    for (int j = j0; j < j1; j++) {
        int snext = (j + 1 < j1) ? g_csrc[j + 1] : 0;
        float sv = g_s2[s];
        float a = sv + dv;
        a = (a > 0.f) ? a : 0.2f * a;
        float ea = __expf(a);
        den += ea;
        float4 hv = *(const float4*)(g_h2 + (size_t)s * OUT_CH + lane * 4);
        a0 = fmaf(ea, hv.x, a0);
        a1 = fmaf(ea, hv.y, a1);
        a2 = fmaf(ea, hv.z, a2);
        a3 = fmaf(ea, hv.w, a3);
        s = snext;
    }
    float inv = 1.f / den;
    int c = lane * 4;
    float v0 = a0 * inv + bias[c + 0];
    float v1 = a1 * inv + bias[c + 1];
    float v2 = a2 * inv + bias[c + 2];
    float v3 = a3 * inv + bias[c + 3];
    v0 = (v0 > 0.f) ? v0 : expm1f(v0);
    v1 = (v1 > 0.f) ? v1 : expm1f(v1);
    v2 = (v2 > 0.f) ? v2 : expm1f(v2);
    v3 = (v3 > 0.f) ? v3 : expm1f(v3);
    *(float4*)(out + (size_t)gw * OUT_CH + c) = make_float4(v0, v1, v2, v3);
}

// ------------------ launch ---------------------------------------------------
extern "C" void kernel_launch(void* const* d_in, const int* in_sizes, int n_in,
                              void* d_out, int out_size)
{
    const float* x   = (const float*)d_in[0];
    const int*   ei  = (const int*)  d_in[1];
    const float* W1  = (const float*)d_in[2];
    const float* as1 = (const float*)d_in[3];
    const float* ad1 = (const float*)d_in[4];
    const float* b1  = (const float*)d_in[5];
    const float* W2  = (const float*)d_in[6];
    const float* as2 = (const float*)d_in[7];
    const float* ad2 = (const float*)d_in[8];
    const float* b2  = (const float*)d_in[9];
    float* out = (float*)d_out;

    int n = in_sizes[0] / IN_CH;
    int e = in_sizes[1] / 2;
    const int* src = ei;
    const int* dst = ei + e;

    void *p_h1, *p_h1b, *p_h2, *p;
    cudaGetSymbolAddress(&p_h1,  g_h1);
    cudaGetSymbolAddress(&p_h1b, g_h1b);
    cudaGetSymbolAddress(&p_h2,  g_h2);

    // ---- CSR build (shared by both layers) ----
    cudaGetSymbolAddress(&p, g_deg);
    cudaMemsetAsync(p, 0, (size_t)n * 4);
    count_kernel<<<(e + n + 255) / 256, 256>>>(dst, e, n);
    scan_kernel<<<1, 1024>>>(n);
    scatter_kernel<<<(e + n + 255) / 256, 256>>>(src, dst, e, n);

    // ---- layer 1 ----
    {
        dim3 grid((n + 127) / 128, H1DIM / 64);
        sgemm128x64<<<grid, 256>>>(x, W1, (float*)p_h1, n, H1DIM, IN_CH);
    }
    sd1_kernel<<<(n * NHEADS + 255) / 256, 256>>>(as1, ad1, n);
    gather1_kernel<<<(n * 32 + 255) / 256, 256>>>(b1, n);

    // ---- layer 2 ----
    {
        dim3 grid((n + 127) / 128, OUT_CH / 64);
        sgemm128x64<<<grid, 256>>>((const float*)p_h1b, W2, (float*)p_h2, n, OUT_CH, H1DIM);
    }
    sd2_kernel<<<(n * 32 + 255) / 256, 256>>>(as2, ad2, n);
    gather2_kernel<<<(n * 32 + 255) / 256, 256>>>(b2, out, n);
}

// round 4
// speedup vs baseline: 2.0744x; 1.0666x over previous
#include <cuda_runtime.h>
#include <math.h>

#define IN_CH   512
#define NHEADS  8
#define H1DIM   64
#define OUT_CH  128
#define NMAX    50000
#define EMAX    800000
#define ETOT    (EMAX + NMAX)

// ------------------ scratch (static device globals; no allocs) ---------------
__device__ float g_h1   [NMAX * H1DIM];
__device__ float g_s1   [NMAX * NHEADS];
__device__ float g_d1   [NMAX * NHEADS];
__device__ float g_h1b  [NMAX * H1DIM];
__device__ float g_h2   [NMAX * OUT_CH];
__device__ float g_s2   [NMAX];
__device__ float g_d2   [NMAX];
__device__ int   g_deg   [NMAX];
__device__ int   g_rowptr[NMAX + 1];
__device__ int   g_cur   [NMAX];
__device__ int   g_csrc  [ETOT];

// ------------------ 3xTF32 tensor-core GEMM ---------------------------------
// C[M,N] = A[M,K] @ B[K,N], fp32 in/out, ~fp32 accuracy via big+small split.
__device__ __forceinline__ unsigned f2tf(float x)
{
    unsigned u;
    asm("cvt.rna.tf32.f32 %0, %1;" : "=r"(u) : "f"(x));
    return u;
}

__device__ __forceinline__ void mma_tf32(float* c, const unsigned* a, const unsigned* b)
{
    asm volatile(
        "mma.sync.aligned.m16n8k8.row.col.f32.tf32.tf32.f32 "
        "{%0,%1,%2,%3}, {%4,%5,%6,%7}, {%8,%9}, {%0,%1,%2,%3};\n"
        : "+f"(c[0]), "+f"(c[1]), "+f"(c[2]), "+f"(c[3])
        : "r"(a[0]), "r"(a[1]), "r"(a[2]), "r"(a[3]), "r"(b[0]), "r"(b[1]));
}

#define GBM 128
#define GBN 64
#define GBK 16

__global__ void __launch_bounds__(256)
gemm_tf32(const float* __restrict__ A, const float* __restrict__ B,
          float* __restrict__ C, int M, int N, int K)
{
    __shared__ float Ah[GBK][GBM + 8], Al[GBK][GBM + 8];
    __shared__ float Bh[GBK][GBN + 8], Bl[GBK][GBN + 8];

    int tid  = threadIdx.x;
    int w    = tid >> 5, lane = tid & 31;
    int g    = lane >> 2, tig = lane & 3;
    int wm   = (w & 3) * 32;
    int wn   = (w >> 2) * 32;
    int m0   = blockIdx.x * GBM;
    int n0   = blockIdx.y * GBN;

    float acc[2][4][4];
#pragma unroll
    for (int i = 0; i < 2; i++)
#pragma unroll
        for (int j = 0; j < 4; j++)
#pragma unroll
            for (int r = 0; r < 4; r++) acc[i][j][r] = 0.f;

    for (int k0 = 0; k0 < K; k0 += GBK) {
        // A tile: 128 rows x 16 k. id -> (q = id>>7 selects k-quad, r = id&127)
#pragma unroll
        for (int i = 0; i < 2; i++) {
            int id = tid + 256 * i;
            int q  = id >> 7;
            int r  = id & 127;
            int gr = m0 + r;
            float4 v = make_float4(0.f, 0.f, 0.f, 0.f);
            if (gr < M) v = *(const float4*)(A + (size_t)gr * K + k0 + q * 4);
            float e[4] = {v.x, v.y, v.z, v.w};
#pragma unroll
            for (int t = 0; t < 4; t++) {
                int k = q * 4 + t;
                unsigned hb = f2tf(e[t]);
                float hf = __uint_as_float(hb);
                Ah[k][r] = hf;
                Al[k][r] = __uint_as_float(f2tf(e[t] - hf));
            }
        }
        // B tile: 16 k x 64 n (one float4/thread)
        {
            int kk = tid >> 4;
            int nq = tid & 15;
            float4 v = *(const float4*)(B + (size_t)(k0 + kk) * N + n0 + nq * 4);
            float e[4] = {v.x, v.y, v.z, v.w};
            float hi[4], lo[4];
#pragma unroll
            for (int t = 0; t < 4; t++) {
                unsigned hb = f2tf(e[t]);
                hi[t] = __uint_as_float(hb);
                lo[t] = __uint_as_float(f2tf(e[t] - hi[t]));
            }
            *(float4*)&Bh[kk][nq * 4] = make_float4(hi[0], hi[1], hi[2], hi[3]);
            *(float4*)&Bl[kk][nq * 4] = make_float4(lo[0], lo[1], lo[2], lo[3]);
        }
        __syncthreads();

#pragma unroll
        for (int ks = 0; ks < GBK; ks += 8) {
            unsigned ah[2][4], bh[4][2], tmp[2][4];
            // hi fragments
#pragma unroll
            for (int i = 0; i < 2; i++) {
                int rb = wm + i * 16;
                ah[i][0] = __float_as_uint(Ah[ks + tig    ][rb + g    ]);
                ah[i][1] = __float_as_uint(Ah[ks + tig    ][rb + g + 8]);
                ah[i][2] = __float_as_uint(Ah[ks + tig + 4][rb + g    ]);
                ah[i][3] = __float_as_uint(Ah[ks + tig + 4][rb + g + 8]);
            }
#pragma unroll
            for (int j = 0; j < 4; j++) {
                int nb = wn + j * 8;
                bh[j][0] = __float_as_uint(Bh[ks + tig    ][nb + g]);
                bh[j][1] = __float_as_uint(Bh[ks + tig + 4][nb + g]);
            }
            // term 1: Ahi * Bhi
#pragma unroll
            for (int i = 0; i < 2; i++)
#pragma unroll
                for (int j = 0; j < 4; j++) mma_tf32(acc[i][j], ah[i], bh[j]);
            // term 2: Alo * Bhi
#pragma unroll
            for (int i = 0; i < 2; i++) {
                int rb = wm + i * 16;
                tmp[i][0] = __float_as_uint(Al[ks + tig    ][rb + g    ]);
                tmp[i][1] = __float_as_uint(Al[ks + tig    ][rb + g + 8]);
                tmp[i][2] = __float_as_uint(Al[ks + tig + 4][rb + g    ]);
                tmp[i][3] = __float_as_uint(Al[ks + tig + 4][rb + g + 8]);
            }
#pragma unroll
            for (int i = 0; i < 2; i++)
#pragma unroll
                for (int j = 0; j < 4; j++) mma_tf32(acc[i][j], tmp[i], bh[j]);
            // term 3: Ahi * Blo
            unsigned bl[4][2];
#pragma unroll
            for (int j = 0; j < 4; j++) {
                int nb = wn + j * 8;
                bl[j][0] = __float_as_uint(Bl[ks + tig    ][nb + g]);
                bl[j][1] = __float_as_uint(Bl[ks + tig + 4][nb + g]);
            }
#pragma unroll
            for (int i = 0; i < 2; i++)
#pragma unroll
                for (int j = 0; j < 4; j++) mma_tf32(acc[i][j], ah[i], bl[j]);
        }
        __syncthreads();
    }

    // epilogue
#pragma unroll
    for (int i = 0; i < 2; i++) {
#pragma unroll
        for (int j = 0; j < 4; j++) {
            int row = m0 + wm + i * 16 + g;
            int col = n0 + wn + j * 8 + 2 * tig;
            if (row < M)
                *(float2*)(C + (size_t)row * N + col) =
                    make_float2(acc[i][j][0], acc[i][j][1]);
            if (row + 8 < M)
                *(float2*)(C + (size_t)(row + 8) * N + col) =
                    make_float2(acc[i][j][2], acc[i][j][3]);
        }
    }
}

// ------------------ CSR build ------------------------------------------------
__global__ void count_kernel(const int* __restrict__ dst, int ne, int n)
{
    int i = blockIdx.x * blockDim.x + threadIdx.x;
    if (i >= ne + n) return;
    int d = (i < ne) ? dst[i] : (i - ne);
    atomicAdd(&g_deg[d], 1);
}

__global__ void __launch_bounds__(1024) scan_kernel(int n)
{
    __shared__ int warpsums[32];
    __shared__ int s_carry;
    int tid = threadIdx.x, lane = tid & 31, wid = tid >> 5;
    if (tid == 0) s_carry = 0;
    __syncthreads();

    for (int base = 0; base < n; base += 4096) {
        int i0 = base + tid * 4;
        int v[4];
#pragma unroll
        for (int k = 0; k < 4; k++) {
            int i = i0 + k;
            v[k] = (i < n) ? g_deg[i] : 0;
        }
        int tsum = v[0] + v[1] + v[2] + v[3];
        int x = tsum;
#pragma unroll
        for (int off = 1; off < 32; off <<= 1) {
            int t = __shfl_up_sync(0xffffffffu, x, off);
            if (lane >= off) x += t;
        }
        if (lane == 31) warpsums[wid] = x;
        __syncthreads();
        if (wid == 0) {
            int wv = warpsums[lane];
#pragma unroll
            for (int off = 1; off < 32; off <<= 1) {
                int t = __shfl_up_sync(0xffffffffu, wv, off);
                if (lane >= off) wv += t;
            }
            warpsums[lane] = wv;
        }
        __syncthreads();
        int warp_off = (wid > 0) ? warpsums[wid - 1] : 0;
        int run = s_carry + warp_off + (x - tsum);
#pragma unroll
        for (int k = 0; k < 4; k++) {
            int i = i0 + k;
            if (i < n) { g_rowptr[i] = run; g_cur[i] = run; }
            run += v[k];
        }
        __syncthreads();
        if (tid == 0) s_carry += warpsums[31];
        __syncthreads();
    }
    if (threadIdx.x == 0) g_rowptr[n] = s_carry;
}

__global__ void scatter_kernel(const int* __restrict__ src,
                               const int* __restrict__ dst, int ne, int n)
{
    int i = blockIdx.x * blockDim.x + threadIdx.x;
    if (i >= ne + n) return;
    int s, d;
    if (i < ne) { s = src[i]; d = dst[i]; }
    else        { s = d = i - ne; }
    int pos = atomicAdd(&g_cur[d], 1);
    g_csrc[pos] = s;
}

// ------------------ layer-1 per-node attention coefficients ------------------
__global__ void sd1_kernel(const float* __restrict__ att_src,
                           const float* __restrict__ att_dst, int n)
{
    int i = blockIdx.x * blockDim.x + threadIdx.x;
    if (i >= n * NHEADS) return;
    int node = i >> 3, h = i & 7;
    const float* hp = g_h1 + node * H1DIM + h * 8;
    float s = 0.f, d = 0.f;
#pragma unroll
    for (int c = 0; c < 8; c++) {
        float v = hp[c];
        s = fmaf(v, att_src[h * 8 + c], s);
        d = fmaf(v, att_dst[h * 8 + c], d);
    }
    g_s1[i] = s;
    g_d1[i] = d;
}

// ------------------ layer-1 gather (4-wide unrolled) -------------------------
__global__ void __launch_bounds__(256) gather1_kernel(const float* __restrict__ bias, int n)
{
    int gw   = (blockIdx.x * blockDim.x + threadIdx.x) >> 5;
    int lane = threadIdx.x & 31;
    if (gw >= n) return;
    int h = lane >> 2;
    float dv = g_d1[gw * NHEADS + h];
    int j0 = g_rowptr[gw], j1 = g_rowptr[gw + 1];
    float acc0 = 0.f, acc1 = 0.f, den = 0.f;
    int j = j0;
    for (; j + 3 < j1; j += 4) {
        int s0 = g_csrc[j], s1 = g_csrc[j + 1], s2 = g_csrc[j + 2], s3 = g_csrc[j + 3];
        float a0 = g_s1[s0 * NHEADS + h] + dv;
        float a1 = g_s1[s1 * NHEADS + h] + dv;
        float a2 = g_s1[s2 * NHEADS + h] + dv;
        float a3 = g_s1[s3 * NHEADS + h] + dv;
        float2 h0 = *(const float2*)(g_h1 + s0 * H1DIM + lane * 2);
        float2 h1 = *(const float2*)(g_h1 + s1 * H1DIM + lane * 2);
        float2 h2 = *(const float2*)(g_h1 + s2 * H1DIM + lane * 2);
        float2 h3 = *(const float2*)(g_h1 + s3 * H1DIM + lane * 2);
        a0 = (a0 > 0.f) ? a0 : 0.2f * a0;  float e0 = __expf(a0);
        a1 = (a1 > 0.f) ? a1 : 0.2f * a1;  float e1 = __expf(a1);
        a2 = (a2 > 0.f) ? a2 : 0.2f * a2;  float e2 = __expf(a2);
        a3 = (a3 > 0.f) ? a3 : 0.2f * a3;  float e3 = __expf(a3);
        den += (e0 + e1) + (e2 + e3);
        acc0 = fmaf(e0, h0.x, acc0); acc1 = fmaf(e0, h0.y, acc1);
        acc0 = fmaf(e1, h1.x, acc0); acc1 = fmaf(e1, h1.y, acc1);
        acc0 = fmaf(e2, h2.x, acc0); acc1 = fmaf(e2, h2.y, acc1);
        acc0 = fmaf(e3, h3.x, acc0); acc1 = fmaf(e3, h3.y, acc1);
    }
    for (; j < j1; j++) {
        int s = g_csrc[j];
        float a = g_s1[s * NHEADS + h] + dv;
        a = (a > 0.f) ? a : 0.2f * a;
        float ea = __expf(a);
        den += ea;
        float2 hv = *(const float2*)(g_h1 + s * H1DIM + lane * 2);
        acc0 = fmaf(ea, hv.x, acc0);
        acc1 = fmaf(ea, hv.y, acc1);
    }
    float inv = 1.f / den;
    int c = lane * 2;
    float v0 = acc0 * inv + bias[c];
    float v1 = acc1 * inv + bias[c + 1];
    v0 = (v0 > 0.f) ? v0 : expm1f(v0);
    v1 = (v1 > 0.f) ? v1 : expm1f(v1);
    *(float2*)(g_h1b + gw * H1DIM + c) = make_float2(v0, v1);
}

// ------------------ layer-2 per-node attention coefficients ------------------
__global__ void sd2_kernel(const float* __restrict__ att_src,
                           const float* __restrict__ att_dst, int n)
{
    int gt   = blockIdx.x * blockDim.x + threadIdx.x;
    int node = gt >> 5;
    int lane = gt & 31;
    if (node >= n) return;
    float4 hv = *(const float4*)(g_h2 + (size_t)node * OUT_CH + lane * 4);
    float4 as = *(const float4*)(att_src + lane * 4);
    float4 ad = *(const float4*)(att_dst + lane * 4);
    float s = hv.x * as.x + hv.y * as.y + hv.z * as.z + hv.w * as.w;
    float d = hv.x * ad.x + hv.y * ad.y + hv.z * ad.z + hv.w * ad.w;
#pragma unroll
    for (int off = 16; off > 0; off >>= 1) {
        s += __shfl_down_sync(0xffffffffu, s, off);
        d += __shfl_down_sync(0xffffffffu, d, off);
    }
    if (lane == 0) { g_s2[node] = s; g_d2[node] = d; }
}

// ------------------ layer-2 gather (4-wide unrolled) -> final output ---------
__global__ void __launch_bounds__(256) gather2_kernel(const float* __restrict__ bias,
                                                      float* __restrict__ out, int n)
{
    int gw   = (blockIdx.x * blockDim.x + threadIdx.x) >> 5;
    int lane = threadIdx.x & 31;
    if (gw >= n) return;
    float dv = g_d2[gw];
    int j0 = g_rowptr[gw], j1 = g_rowptr[gw + 1];
    float a0 = 0.f, a1 = 0.f, a2 = 0.f, a3 = 0.f, den = 0.f;
    int j = j0;
    for (; j + 3 < j1; j += 4) {
        int s0 = g_csrc[j], s1 = g_csrc[j + 1], s2 = g_csrc[j + 2], s3 = g_csrc[j + 3];
        float x0 = g_s2[s0] + dv, x1 = g_s2[s1] + dv;
        float x2 = g_s2[s2] + dv, x3 = g_s2[s3] + dv;
        float4 h0 = *(const float4*)(g_h2 + (size_t)s0 * OUT_CH + lane * 4);
        float4 h1 = *(const float4*)(g_h2 + (size_t)s1 * OUT_CH + lane * 4);
        float4 h2 = *(const float4*)(g_h2 + (size_t)s2 * OUT_CH + lane * 4);
        float4 h3 = *(const float4*)(g_h2 + (size_t)s3 * OUT_CH + lane * 4);
        x0 = (x0 > 0.f) ? x0 : 0.2f * x0;  float e0 = __expf(x0);
        x1 = (x1 > 0.f) ? x1 : 0.2f * x1;  float e1 = __expf(x1);
        x2 = (x2 > 0.f) ? x2 : 0.2f * x2;  float e2 = __expf(x2);
        x3 = (x3 > 0.f) ? x3 : 0.2f * x3;  float e3 = __expf(x3);
        den += (e0 + e1) + (e2 + e3);
        a0 = fmaf(e0, h0.x, a0); a1 = fmaf(e0, h0.y, a1);
        a2 = fmaf(e0, h0.z, a2); a3 = fmaf(e0, h0.w, a3);
        a0 = fmaf(e1, h1.x, a0); a1 = fmaf(e1, h1.y, a1);
        a2 = fmaf(e1, h1.z, a2); a3 = fmaf(e1, h1.w, a3);
        a0 = fmaf(e2, h2.x, a0); a1 = fmaf(e2, h2.y, a1);
        a2 = fmaf(e2, h2.z, a2); a3 = fmaf(e2, h2.w, a3);
        a0 = fmaf(e3, h3.x, a0); a1 = fmaf(e3, h3.y, a1);
        a2 = fmaf(e3, h3.z, a2); a3 = fmaf(e3, h3.w, a3);
    }
    for (; j < j1; j++) {
        int s = g_csrc[j];
        float x = g_s2[s] + dv;
        x = (x > 0.f) ? x : 0.2f * x;
        float ea = __expf(x);
        den += ea;
        float4 hv = *(const float4*)(g_h2 + (size_t)s * OUT_CH + lane * 4);
        a0 = fmaf(ea, hv.x, a0);
        a1 = fmaf(ea, hv.y, a1);
        a2 = fmaf(ea, hv.z, a2);
        a3 = fmaf(ea, hv.w, a3);
    }
    float inv = 1.f / den;
    int c = lane * 4;
    float v0 = a0 * inv + bias[c + 0];
    float v1 = a1 * inv + bias[c + 1];
    float v2 = a2 * inv + bias[c + 2];
    float v3 = a3 * inv + bias[c + 3];
    v0 = (v0 > 0.f) ? v0 : expm1f(v0);
    v1 = (v1 > 0.f) ? v1 : expm1f(v1);
    v2 = (v2 > 0.f) ? v2 : expm1f(v2);
    v3 = (v3 > 0.f) ? v3 : expm1f(v3);
    *(float4*)(out + (size_t)gw * OUT_CH + c) = make_float4(v0, v1, v2, v3);
}

// ------------------ launch ---------------------------------------------------
extern "C" void kernel_launch(void* const* d_in, const int* in_sizes, int n_in,
                              void* d_out, int out_size)
{
    const float* x   = (const float*)d_in[0];
    const int*   ei  = (const int*)  d_in[1];
    const float* W1  = (const float*)d_in[2];
    const float* as1 = (const float*)d_in[3];
    const float* ad1 = (const float*)d_in[4];
    const float* b1  = (const float*)d_in[5];
    const float* W2  = (const float*)d_in[6];
    const float* as2 = (const float*)d_in[7];
    const float* ad2 = (const float*)d_in[8];
    const float* b2  = (const float*)d_in[9];
    float* out = (float*)d_out;

    int n = in_sizes[0] / IN_CH;
    int e = in_sizes[1] / 2;
    const int* src = ei;
    const int* dst = ei + e;

    void *p_h1, *p_h1b, *p_h2, *p;
    cudaGetSymbolAddress(&p_h1,  g_h1);
    cudaGetSymbolAddress(&p_h1b, g_h1b);
    cudaGetSymbolAddress(&p_h2,  g_h2);

    // ---- CSR build (shared by both layers) ----
    cudaGetSymbolAddress(&p, g_deg);
    cudaMemsetAsync(p, 0, (size_t)n * 4);
    count_kernel<<<(e + n + 255) / 256, 256>>>(dst, e, n);
    scan_kernel<<<1, 1024>>>(n);
    scatter_kernel<<<(e + n + 255) / 256, 256>>>(src, dst, e, n);

    // ---- layer 1 ----
    {
        dim3 grid((n + GBM - 1) / GBM, H1DIM / GBN);
        gemm_tf32<<<grid, 256>>>(x, W1, (float*)p_h1, n, H1DIM, IN_CH);
    }
    sd1_kernel<<<(n * NHEADS + 255) / 256, 256>>>(as1, ad1, n);
    gather1_kernel<<<(n * 32 + 255) / 256, 256>>>(b1, n);

    // ---- layer 2 ----
    {
        dim3 grid((n + GBM - 1) / GBM, OUT_CH / GBN);
        gemm_tf32<<<grid, 256>>>((const float*)p_h1b, W2, (float*)p_h2, n, OUT_CH, H1DIM);
    }
    sd2_kernel<<<(n * 32 + 255) / 256, 256>>>(as2, ad2, n);
    gather2_kernel<<<(n * 32 + 255) / 256, 256>>>(b2, out, n);
}